// round 10
// baseline (speedup 1.0000x reference)
#include <cuda_runtime.h>
#include <math.h>
#include <stdint.h>

#define DIM   4096
#define NH    32
#define NKV   8
#define G     4
#define HD    128
#define INTER 14336
#define PS    16
#define B     32
#define QKV_M ((NH + 2*NKV) * HD)   // 6144
#define EPS   1e-5f
#define SCALE 0.08838834764831845f  // 1/sqrt(128)

#define SPLIT 8      // attention split-KV
#define SQKV  8      // split-K qkv  (K=4096 -> 512)
#define SWO   8      // split-K wo   (K=4096 -> 512)
#define SW1   4      // split-K w1   (K=4096 -> 1024)
#define SW2   8      // split-K w2   (K=14336 -> 1792)

// ------------------------- device scratch -------------------------
__device__ float g_xa  [B * DIM];                  // rmsnorm(x)  [b][k]
__device__ float g_qkvP[SQKV * B * QKV_M];         // qkv partials [s][b][m]
__device__ float g_q   [B * NH * HD];
__device__ float g_kn  [B * NKV * HD];
__device__ float g_vn  [B * NKV * HD];
__device__ float g_pO  [B * NKV * SPLIT * G * HD];
__device__ float g_pL  [B * NKV * SPLIT * G];
__device__ float g_o   [B * NH * HD];              // attn out [b][k]
__device__ float g_woP [SWO * B * DIM];
__device__ float g_h   [B * DIM];
__device__ float g_hf  [B * DIM];
__device__ float g_w1P [SW1 * B * INTER];
__device__ float g_g   [B * INTER];
__device__ float g_w2P [SW2 * B * DIM];

// ------------------------- helpers -------------------------
static __device__ __forceinline__ void mma8(float* d,
        uint32_t a0, uint32_t a1, uint32_t a2, uint32_t a3,
        uint32_t b0, uint32_t b1) {
    asm volatile("mma.sync.aligned.m16n8k8.row.col.f32.tf32.tf32.f32 "
        "{%0,%1,%2,%3}, {%4,%5,%6,%7}, {%8,%9}, {%0,%1,%2,%3};"
        : "+f"(d[0]), "+f"(d[1]), "+f"(d[2]), "+f"(d[3])
        : "r"(a0), "r"(a1), "r"(a2), "r"(a3), "r"(b0), "r"(b1));
}
static __device__ __forceinline__ void cpa16(uint32_t s, const void* g) {
    asm volatile("cp.async.cg.shared.global [%0], [%1], 16;" :: "r"(s), "l"(g));
}
static __device__ __forceinline__ uint32_t fbits(float f) {
    return __float_as_uint(f);
}

__device__ __forceinline__ float blockReduceSum256(float v) {
    __shared__ float sh[8];
    int lane = threadIdx.x & 31, w = threadIdx.x >> 5;
    #pragma unroll
    for (int o = 16; o; o >>= 1) v += __shfl_xor_sync(0xffffffffu, v, o);
    if (lane == 0) sh[w] = v;
    __syncthreads();
    if (threadIdx.x == 0) {
        float total = sh[0];
        #pragma unroll
        for (int i = 1; i < 8; i++) total += sh[i];
        sh[0] = total;
    }
    __syncthreads();
    float total = sh[0];
    __syncthreads();
    return total;
}

// ------------------------- kernel 1: rmsnorm(x) -> g_xa [b][k] -------------------------
__global__ __launch_bounds__(256) void k_rms_x(const float* __restrict__ x,
                                               const float* __restrict__ w) {
    int b = blockIdx.x, tid = threadIdx.x;
    float v[16];
    float ss = 0.f;
    #pragma unroll
    for (int i = 0; i < 16; i++) {
        float t = x[b * DIM + tid + i * 256];
        v[i] = t; ss += t * t;
    }
    ss = blockReduceSum256(ss);
    float r = rsqrtf(ss / (float)DIM + EPS);
    #pragma unroll
    for (int i = 0; i < 16; i++) {
        int m = tid + i * 256;
        g_xa[(size_t)b * DIM + m] = v[i] * r * w[m];
    }
}

// ------------------------- tf32 mma.sync split-K GEMM, 3-stage cp.async ----------
// P[(s*B+n)*M + m] = sum_{k in split s} W[m][k] * X[n][k]
// 128 thr (4 warps x 16 m-rows), BM=64, BK=32, 3 SMEM stages, ONE sync per chunk.
__global__ __launch_bounds__(128) void k_gemm_mma(const float* __restrict__ W,
                                                  const float* __restrict__ X,
                                                  float* __restrict__ P,
                                                  int M, int K, int kps) {
    __shared__ float Ws[3][64 * 36];
    __shared__ float Xs[3][32 * 36];
    const int tid = threadIdx.x;
    const int lane = tid & 31, wid = tid >> 5;
    const int wm = wid * 16;
    const int g = lane >> 2, c = lane & 3;
    const int m0 = blockIdx.x * 64;
    const int kb = blockIdx.y * kps;
    const int NC = kps / 32;

    float acc[4][4];
    #pragma unroll
    for (int nt = 0; nt < 4; nt++)
        acc[nt][0] = acc[nt][1] = acc[nt][2] = acc[nt][3] = 0.f;

    // staging: A = 64x32 floats (512 x 16B), X = 32x32 (256 x 16B)
    const int r1 = tid >> 3;
    const int j1 = (tid & 7) * 4;

    auto stage = [&](int buf, int kc) {
        #pragma unroll
        for (int i = 0; i < 4; i++) {
            int rr = i * 16 + r1;
            cpa16((uint32_t)__cvta_generic_to_shared(&Ws[buf][rr * 36 + j1]),
                  W + (size_t)(m0 + rr) * K + kc + j1);
        }
        #pragma unroll
        for (int i = 0; i < 2; i++) {
            int rr = i * 16 + r1;
            cpa16((uint32_t)__cvta_generic_to_shared(&Xs[buf][rr * 36 + j1]),
                  X + (size_t)rr * K + kc + j1);
        }
        asm volatile("cp.async.commit_group;" ::: "memory");
    };

    stage(0, kb);
    stage(1, kb + 32);

    for (int cc = 0; cc < NC; cc++) {
        if (cc + 1 < NC) asm volatile("cp.async.wait_group 1;" ::: "memory");
        else             asm volatile("cp.async.wait_group 0;" ::: "memory");
        __syncthreads();
        if (cc + 2 < NC)
            stage((cc + 2) % 3, kb + (cc + 2) * 32);
        const float* WsB = Ws[cc % 3];
        const float* XsB = Xs[cc % 3];
        #pragma unroll
        for (int ks = 0; ks < 4; ks++) {
            int kA0 = ks * 8 + c, kA1 = kA0 + 4;
            uint32_t a0 = fbits(WsB[(wm + g) * 36 + kA0]);
            uint32_t a1 = fbits(WsB[(wm + g + 8) * 36 + kA0]);
            uint32_t a2 = fbits(WsB[(wm + g) * 36 + kA1]);
            uint32_t a3 = fbits(WsB[(wm + g + 8) * 36 + kA1]);
            #pragma unroll
            for (int nt = 0; nt < 4; nt++) {
                uint32_t b0 = fbits(XsB[(nt * 8 + g) * 36 + kA0]);
                uint32_t b1 = fbits(XsB[(nt * 8 + g) * 36 + kA1]);
                mma8(acc[nt], a0, a1, a2, a3, b0, b1);
            }
        }
    }

    // epilogue: m16n8k8 C layout -> P[s][n][m]
    float* pb = P + (size_t)blockIdx.y * B * M;
    int mlo = m0 + wm + g;
    #pragma unroll
    for (int nt = 0; nt < 4; nt++) {
        int col = nt * 8 + 2 * c;
        pb[(size_t)(col)     * M + mlo]     = acc[nt][0];
        pb[(size_t)(col + 1) * M + mlo]     = acc[nt][1];
        pb[(size_t)(col)     * M + mlo + 8] = acc[nt][2];
        pb[(size_t)(col + 1) * M + mlo + 8] = acc[nt][3];
    }
}

// ------------------------- kernel 3: combine qkv partials + rope -------------------------
__global__ __launch_bounds__(128) void k_rope(const int* __restrict__ offsets) {
    int b = blockIdx.x, hh = blockIdx.y, d = threadIdx.x;
    __shared__ float sm[HD];
    int m = hh * HD + d;
    float v = 0.f;
    #pragma unroll
    for (int s = 0; s < SQKV; s++)
        v += g_qkvP[((size_t)s * B + b) * QKV_M + m];
    sm[d] = v;
    __syncthreads();
    if (hh < NH + NKV) {
        int j = (d & 63);
        double inv = exp(-((double)j / 64.0) * log(10000.0));
        double ang = (double)offsets[b] * inv;
        double si, co;
        sincos(ang, &si, &co);
        float out;
        if (d < 64) out = sm[d] * (float)co - sm[d + 64] * (float)si;
        else        out = sm[d - 64] * (float)si + sm[d] * (float)co;
        if (hh < NH)
            g_q[(size_t)b * NH * HD + hh * HD + d] = out * SCALE;
        else
            g_kn[(size_t)b * NKV * HD + (hh - NH) * HD + d] = out;
    } else {
        g_vn[(size_t)b * NKV * HD + (hh - NH - NKV) * HD + d] = v;
    }
}

// ------------------------- kernel 4: flash attention, split-KV, absolute-exp -------
__global__ __launch_bounds__(128) void k_attn(const float* __restrict__ pk,
                                              const float* __restrict__ pv,
                                              const int* __restrict__ pidx,
                                              const int* __restrict__ pindptr,
                                              const int* __restrict__ plast) {
    int s = blockIdx.x, kvh = blockIdx.y, b = blockIdx.z;
    int tid = threadIdx.x, w = tid >> 5, lane = tid & 31;
    __shared__ float smq[G * HD];
    __shared__ float so[4][G][HD];
    __shared__ float sl[4][G];

    for (int i = tid; i < G * HD; i += 128)
        smq[i] = g_q[(size_t)b * NH * HD + (kvh * G) * HD + i];
    __syncthreads();
    float4 q[G];
    #pragma unroll
    for (int h = 0; h < G; h++) q[h] = *(float4*)&smq[h * HD + lane * 4];

    int p0 = pindptr[b];
    int npages = pindptr[b + 1] - p0;
    int kvlen = (npages - 1) * PS + plast[b];
    int chunk = (kvlen + SPLIT - 1) / SPLIT;
    int cs = s * chunk, ce = min(cs + chunk, kvlen);
    int kvm1 = kvlen - 1;
    int ce2 = min(ce, kvm1);

    float lv[G];
    float4 o[G];
    #pragma unroll
    for (int h = 0; h < G; h++) {
        lv[h] = 0.f; o[h] = make_float4(0.f, 0.f, 0.f, 0.f);
    }

    for (int pos = cs + w * 2; pos < ce2; pos += 8) {
        int pg0 = pidx[p0 + (pos >> 4)];
        size_t ba = (((size_t)pg0 * PS + (pos & 15)) * NKV + kvh) * HD;
        float4 k4a = *(const float4*)(pk + ba + lane * 4);
        float4 v4a = *(const float4*)(pv + ba + lane * 4);
        int pos1 = pos + 1;
        bool h1 = pos1 < ce2;
        float4 k4b = make_float4(0.f, 0.f, 0.f, 0.f);
        float4 v4b = k4b;
        if (h1) {
            int pg1 = pidx[p0 + (pos1 >> 4)];
            size_t bb = (((size_t)pg1 * PS + (pos1 & 15)) * NKV + kvh) * HD;
            k4b = *(const float4*)(pk + bb + lane * 4);
            v4b = *(const float4*)(pv + bb + lane * 4);
        }
        float sa[G], sb[G];
        #pragma unroll
        for (int h = 0; h < G; h++) {
            sa[h] = q[h].x * k4a.x + q[h].y * k4a.y + q[h].z * k4a.z + q[h].w * k4a.w;
            sb[h] = q[h].x * k4b.x + q[h].y * k4b.y + q[h].z * k4b.z + q[h].w * k4b.w;
        }
        #pragma unroll
        for (int off = 16; off; off >>= 1) {
            #pragma unroll
            for (int h = 0; h < G; h++) {
                sa[h] += __shfl_xor_sync(0xffffffffu, sa[h], off);
                sb[h] += __shfl_xor_sync(0xffffffffu, sb[h], off);
            }
        }
        #pragma unroll
        for (int h = 0; h < G; h++) {
            float p = __expf(sa[h]);
            lv[h] += p;
            o[h].x += p * v4a.x;
            o[h].y += p * v4a.y;
            o[h].z += p * v4a.z;
            o[h].w += p * v4a.w;
        }
        if (h1) {
            #pragma unroll
            for (int h = 0; h < G; h++) {
                float p = __expf(sb[h]);
                lv[h] += p;
                o[h].x += p * v4b.x;
                o[h].y += p * v4b.y;
                o[h].z += p * v4b.z;
                o[h].w += p * v4b.w;
            }
        }
    }

    // appended token (position kvlen-1): warp 0 of the owning split
    if (ce == kvlen && cs < kvlen && w == 0) {
        const float* kp = g_kn + ((size_t)b * NKV + kvh) * HD;
        const float* vp = g_vn + ((size_t)b * NKV + kvh) * HD;
        float4 k4 = *(const float4*)(kp + lane * 4);
        float4 v4 = *(const float4*)(vp + lane * 4);
        float sc[G];
        #pragma unroll
        for (int h = 0; h < G; h++)
            sc[h] = q[h].x * k4.x + q[h].y * k4.y + q[h].z * k4.z + q[h].w * k4.w;
        #pragma unroll
        for (int off = 16; off; off >>= 1)
            #pragma unroll
            for (int h = 0; h < G; h++)
                sc[h] += __shfl_xor_sync(0xffffffffu, sc[h], off);
        #pragma unroll
        for (int h = 0; h < G; h++) {
            float p = __expf(sc[h]);
            lv[h] += p;
            o[h].x += p * v4.x;
            o[h].y += p * v4.y;
            o[h].z += p * v4.z;
            o[h].w += p * v4.w;
        }
    }

    #pragma unroll
    for (int h = 0; h < G; h++) {
        so[w][h][lane * 4 + 0] = o[h].x;
        so[w][h][lane * 4 + 1] = o[h].y;
        so[w][h][lane * 4 + 2] = o[h].z;
        so[w][h][lane * 4 + 3] = o[h].w;
        if (lane == 0) sl[w][h] = lv[h];
    }
    __syncthreads();

    size_t pbase = (size_t)(b * NKV + kvh) * SPLIT + s;
    for (int h = 0; h < G; h++) {
        float Ls = sl[0][h] + sl[1][h] + sl[2][h] + sl[3][h];
        float Od = so[0][h][tid] + so[1][h][tid] + so[2][h][tid] + so[3][h][tid];
        g_pO[(pbase * G + h) * HD + tid] = Od;
        if (tid == 0) g_pL[pbase * G + h] = Ls;
    }
}

// ------------------------- kernel 5: combine attention splits -> g_o [b][k] ----------
__global__ __launch_bounds__(128) void k_attn_comb() {
    int hh = blockIdx.x, b = blockIdx.y, d = threadIdx.x;
    int kvh = hh >> 2, h = hh & 3;
    size_t base0 = (size_t)(b * NKV + kvh) * SPLIT;
    float L = 0.f, Od = 0.f;
    #pragma unroll
    for (int s = 0; s < SPLIT; s++) {
        L  += g_pL[(base0 + s) * G + h];
        Od += g_pO[((base0 + s) * G + h) * HD + d];
    }
    g_o[(size_t)b * NH * HD + hh * HD + d] = Od / L;
}

// ------------------------- kernel 7: h = x + woP; hf = rmsnorm(h) -------------------------
__global__ __launch_bounds__(256) void k_resid1(const float* __restrict__ x,
                                                const float* __restrict__ fw) {
    int b = blockIdx.x, tid = threadIdx.x;
    float hv[16];
    float ss = 0.f;
    #pragma unroll
    for (int i = 0; i < 16; i++) {
        int m = tid + i * 256;
        float t = x[b * DIM + m];
        #pragma unroll
        for (int s = 0; s < SWO; s++)
            t += g_woP[((size_t)s * B + b) * DIM + m];
        hv[i] = t; ss += t * t;
        g_h[(size_t)b * DIM + m] = t;
    }
    ss = blockReduceSum256(ss);
    float r = rsqrtf(ss / (float)DIM + EPS);
    #pragma unroll
    for (int i = 0; i < 16; i++) {
        int m = tid + i * 256;
        g_hf[(size_t)b * DIM + m] = hv[i] * r * fw[m];
    }
}

// ------------------------- kernel 9: silu(w1P) * stem -> g_g [b][k] -------------------------
__global__ __launch_bounds__(256) void k_silu(const float* __restrict__ buffer,
                                              const int* __restrict__ bids) {
    int m = blockIdx.x * 256 + threadIdx.x;
    int b = blockIdx.y;
    float v = 0.f;
    #pragma unroll
    for (int s = 0; s < SW1; s++)
        v += g_w1P[((size_t)s * B + b) * INTER + m];
    float sig = 1.f / (1.f + expf(-v));
    float stem = buffer[(size_t)bids[b] * INTER + m];
    g_g[(size_t)b * INTER + m] = v * sig * stem;
}

// ------------------------- kernel 11: out = h + w2P -------------------------
__global__ __launch_bounds__(256) void k_final(float* __restrict__ out) {
    int idx = blockIdx.x * 256 + threadIdx.x;   // idx = b*DIM + m
    float v = g_h[idx];
    #pragma unroll
    for (int s = 0; s < SW2; s++)
        v += g_w2P[(size_t)s * B * DIM + idx];
    out[idx] = v;
}

// ------------------------- launch -------------------------
extern "C" void kernel_launch(void* const* d_in, const int* in_sizes, int n_in,
                              void* d_out, int out_size) {
    (void)in_sizes; (void)n_in; (void)out_size;
    const float* x        = (const float*)d_in[0];
    const float* buffer   = (const float*)d_in[1];
    const float* paged_k  = (const float*)d_in[2];
    const float* paged_v  = (const float*)d_in[3];
    const float* wqkv     = (const float*)d_in[4];
    const float* wo       = (const float*)d_in[5];
    const float* w1       = (const float*)d_in[6];
    const float* w2       = (const float*)d_in[7];
    const float* attn_w   = (const float*)d_in[8];
    const float* ffn_w    = (const float*)d_in[9];
    const int*   bids     = (const int*)d_in[10];
    const int*   offsets  = (const int*)d_in[11];
    const int*   pidx     = (const int*)d_in[13];
    const int*   pindptr  = (const int*)d_in[14];
    const int*   plast    = (const int*)d_in[15];
    float* out = (float*)d_out;

    float* xa;   cudaGetSymbolAddress((void**)&xa,   g_xa);
    float* qkvP; cudaGetSymbolAddress((void**)&qkvP, g_qkvP);
    float* oA;   cudaGetSymbolAddress((void**)&oA,   g_o);
    float* woP;  cudaGetSymbolAddress((void**)&woP,  g_woP);
    float* hf;   cudaGetSymbolAddress((void**)&hf,   g_hf);
    float* w1P;  cudaGetSymbolAddress((void**)&w1P,  g_w1P);
    float* gg;   cudaGetSymbolAddress((void**)&gg,   g_g);
    float* w2P;  cudaGetSymbolAddress((void**)&w2P,  g_w2P);

    k_rms_x<<<B, 256>>>(x, attn_w);
    k_gemm_mma<<<dim3(QKV_M / 64, SQKV), 128>>>(wqkv, xa, qkvP, QKV_M, DIM, DIM / SQKV);
    k_rope<<<dim3(B, 48), 128>>>(offsets);
    k_attn<<<dim3(SPLIT, NKV, B), 128>>>(paged_k, paged_v, pidx, pindptr, plast);
    k_attn_comb<<<dim3(NH, B), 128>>>();
    k_gemm_mma<<<dim3(DIM / 64, SWO), 128>>>(wo, oA, woP, DIM, NH * HD, (NH * HD) / SWO);
    k_resid1<<<B, 256>>>(x, ffn_w);
    k_gemm_mma<<<dim3(INTER / 64, SW1), 128>>>(w1, hf, w1P, INTER, DIM, DIM / SW1);
    k_silu<<<dim3(INTER / 256, B), 256>>>(buffer, bids);
    k_gemm_mma<<<dim3(DIM / 64, SW2), 128>>>(w2, gg, w2P, DIM, INTER, INTER / SW2);
    k_final<<<(B * DIM) / 256, 256>>>(out);
}

// round 12
// speedup vs baseline: 1.0382x; 1.0382x over previous
#include <cuda_runtime.h>
#include <math.h>
#include <stdint.h>

#define DIM   4096
#define NH    32
#define NKV   8
#define G     4
#define HD    128
#define INTER 14336
#define PS    16
#define B     32
#define QKV_M ((NH + 2*NKV) * HD)   // 6144
#define EPS   1e-5f
#define SCALE 0.08838834764831845f  // 1/sqrt(128)

#define SPLIT 8      // attention split-KV
#define SQKV  8      // split-K qkv  (K=4096 -> 512)
#define SWO   16     // split-K wo   (K=4096 -> 256)
#define SW1   4      // split-K w1   (K=4096 -> 1024)
#define SW2   16     // split-K w2   (K=14336 -> 896)

// ------------------------- device scratch -------------------------
__device__ float g_xa  [B * DIM];                  // rmsnorm(x)  [b][k]
__device__ float g_qkvP[SQKV * B * QKV_M];         // qkv partials [s][b][m]
__device__ float g_q   [B * NH * HD];
__device__ float g_kn  [B * NKV * HD];
__device__ float g_vn  [B * NKV * HD];
__device__ float g_pO  [B * NKV * SPLIT * G * HD];
__device__ float g_pL  [B * NKV * SPLIT * G];
__device__ float g_o   [B * NH * HD];              // attn out [b][k]
__device__ float g_woP [SWO * B * DIM];
__device__ float g_h   [B * DIM];
__device__ float g_hf  [B * DIM];
__device__ float g_w1P [SW1 * B * INTER];
__device__ float g_g   [B * INTER];
__device__ float g_w2P [SW2 * B * DIM];

// ------------------------- helpers -------------------------
static __device__ __forceinline__ void mma8(float* d,
        uint32_t a0, uint32_t a1, uint32_t a2, uint32_t a3,
        uint32_t b0, uint32_t b1) {
    asm volatile("mma.sync.aligned.m16n8k8.row.col.f32.tf32.tf32.f32 "
        "{%0,%1,%2,%3}, {%4,%5,%6,%7}, {%8,%9}, {%0,%1,%2,%3};"
        : "+f"(d[0]), "+f"(d[1]), "+f"(d[2]), "+f"(d[3])
        : "r"(a0), "r"(a1), "r"(a2), "r"(a3), "r"(b0), "r"(b1));
}
static __device__ __forceinline__ void ldsm4(uint32_t addr,
        uint32_t& r0, uint32_t& r1, uint32_t& r2, uint32_t& r3) {
    asm volatile("ldmatrix.sync.aligned.m8n8.x4.shared.b16 {%0,%1,%2,%3}, [%4];"
        : "=r"(r0), "=r"(r1), "=r"(r2), "=r"(r3) : "r"(addr));
}
static __device__ __forceinline__ void cpa16(uint32_t s, const void* g) {
    asm volatile("cp.async.cg.shared.global [%0], [%1], 16;" :: "r"(s), "l"(g));
}

__device__ __forceinline__ float blockReduceSum256(float v) {
    __shared__ float sh[8];
    int lane = threadIdx.x & 31, w = threadIdx.x >> 5;
    #pragma unroll
    for (int o = 16; o; o >>= 1) v += __shfl_xor_sync(0xffffffffu, v, o);
    if (lane == 0) sh[w] = v;
    __syncthreads();
    if (threadIdx.x == 0) {
        float total = sh[0];
        #pragma unroll
        for (int i = 1; i < 8; i++) total += sh[i];
        sh[0] = total;
    }
    __syncthreads();
    float total = sh[0];
    __syncthreads();
    return total;
}

// ------------------------- kernel 1: rmsnorm(x) -> g_xa [b][k] -------------------------
__global__ __launch_bounds__(256) void k_rms_x(const float* __restrict__ x,
                                               const float* __restrict__ w) {
    int b = blockIdx.x, tid = threadIdx.x;
    float v[16];
    float ss = 0.f;
    #pragma unroll
    for (int i = 0; i < 16; i++) {
        float t = x[b * DIM + tid + i * 256];
        v[i] = t; ss += t * t;
    }
    ss = blockReduceSum256(ss);
    float r = rsqrtf(ss / (float)DIM + EPS);
    #pragma unroll
    for (int i = 0; i < 16; i++) {
        int m = tid + i * 256;
        g_xa[(size_t)b * DIM + m] = v[i] * r * w[m];
    }
}

// ------------------------- tf32 mma.sync split-K GEMM, ldmatrix fragments ----------
// P[(s*B+n)*M + m] = sum_{k in split s} W[m][k] * X[n][k]
// 256 thr (8 warps x 16 m-rows), BM=128, BK=32, 2-stage cp.async,
// [row][k] SMEM stride 36 floats; fragments via ldmatrix.x4 (3 per k-step).
__global__ __launch_bounds__(256) void k_gemm_mma(const float* __restrict__ W,
                                                  const float* __restrict__ X,
                                                  float* __restrict__ P,
                                                  int M, int K, int kps) {
    __shared__ float Ws[2][128 * 36];
    __shared__ float Xs[2][32 * 36];
    const int tid = threadIdx.x;
    const int lane = tid & 31, wid = tid >> 5;
    const int wm = wid * 16;
    const int g = lane >> 2, c = lane & 3;
    const int m0 = blockIdx.x * 128;
    const int kb = blockIdx.y * kps;
    const int NC = kps / 32;

    float acc[4][4];
    #pragma unroll
    for (int nt = 0; nt < 4; nt++)
        acc[nt][0] = acc[nt][1] = acc[nt][2] = acc[nt][3] = 0.f;

    // staging indices
    const int r1 = tid >> 3;          // 0..31
    const int j1 = (tid & 7) * 4;     // k offset of 16B chunk

    // ldmatrix lane addresses
    const int lr = lane & 7, sel = lane >> 3;
    // A: mat0=a0(rows wm..wm+7, col 0), mat1=a1(+8 rows), mat2=a2(col+4), mat3=a3(both)
    const int arow = wm + ((sel & 1) ? 8 : 0) + lr;
    const int acol = (sel >> 1) * 4;
    // B pair ntp: mat0=b0(nt=2ntp), mat1=b1(nt=2ntp), mat2=b0(nt=2ntp+1), mat3=b1(...)
    const int brow0 = ((sel >> 1) * 8) + lr;        // + ntp*16
    const int bcol  = (sel & 1) * 4;

    uint32_t aA[2], bA0[2], bA1[2];
    #pragma unroll
    for (int bf = 0; bf < 2; bf++) {
        aA[bf]  = (uint32_t)__cvta_generic_to_shared(&Ws[bf][arow * 36 + acol]);
        bA0[bf] = (uint32_t)__cvta_generic_to_shared(&Xs[bf][brow0 * 36 + bcol]);
        bA1[bf] = (uint32_t)__cvta_generic_to_shared(&Xs[bf][(16 + brow0) * 36 + bcol]);
    }

    auto stage = [&](int buf, int kc) {
        #pragma unroll
        for (int i = 0; i < 4; i++) {
            int rr = i * 32 + r1;
            cpa16((uint32_t)__cvta_generic_to_shared(&Ws[buf][rr * 36 + j1]),
                  W + (size_t)(m0 + rr) * K + kc + j1);
        }
        cpa16((uint32_t)__cvta_generic_to_shared(&Xs[buf][r1 * 36 + j1]),
              X + (size_t)r1 * K + kc + j1);
        asm volatile("cp.async.commit_group;" ::: "memory");
    };

    stage(0, kb);
    if (NC > 1) stage(1, kb + 32);

    for (int cc = 0; cc < NC; cc++) {
        if (cc + 1 < NC) asm volatile("cp.async.wait_group 1;" ::: "memory");
        else             asm volatile("cp.async.wait_group 0;" ::: "memory");
        __syncthreads();
        int buf = cc & 1;
        #pragma unroll
        for (int ks = 0; ks < 4; ks++) {
            uint32_t a0, a1, a2, a3;
            ldsm4(aA[buf] + ks * 32, a0, a1, a2, a3);
            uint32_t b00, b01, b10, b11;
            ldsm4(bA0[buf] + ks * 32, b00, b01, b10, b11);
            uint32_t b20, b21, b30, b31;
            ldsm4(bA1[buf] + ks * 32, b20, b21, b30, b31);
            mma8(acc[0], a0, a1, a2, a3, b00, b01);
            mma8(acc[1], a0, a1, a2, a3, b10, b11);
            mma8(acc[2], a0, a1, a2, a3, b20, b21);
            mma8(acc[3], a0, a1, a2, a3, b30, b31);
        }
        __syncthreads();
        if (cc + 2 < NC)
            stage(buf, kb + (cc + 2) * 32);
    }

    // epilogue: m16n8k8 C layout -> P[s][n][m]
    float* pb = P + (size_t)blockIdx.y * B * M;
    int mlo = m0 + wm + g;
    #pragma unroll
    for (int nt = 0; nt < 4; nt++) {
        int col = nt * 8 + 2 * c;
        pb[(size_t)(col)     * M + mlo]     = acc[nt][0];
        pb[(size_t)(col + 1) * M + mlo]     = acc[nt][1];
        pb[(size_t)(col)     * M + mlo + 8] = acc[nt][2];
        pb[(size_t)(col + 1) * M + mlo + 8] = acc[nt][3];
    }
}

// ------------------------- kernel 3: combine qkv partials + rope -------------------------
__global__ __launch_bounds__(128) void k_rope(const int* __restrict__ offsets) {
    int b = blockIdx.x, hh = blockIdx.y, d = threadIdx.x;
    __shared__ float sm[HD];
    int m = hh * HD + d;
    float v = 0.f;
    #pragma unroll
    for (int s = 0; s < SQKV; s++)
        v += g_qkvP[((size_t)s * B + b) * QKV_M + m];
    sm[d] = v;
    __syncthreads();
    if (hh < NH + NKV) {
        int j = (d & 63);
        double inv = exp(-((double)j / 64.0) * log(10000.0));
        double ang = (double)offsets[b] * inv;
        double si, co;
        sincos(ang, &si, &co);
        float out;
        if (d < 64) out = sm[d] * (float)co - sm[d + 64] * (float)si;
        else        out = sm[d - 64] * (float)si + sm[d] * (float)co;
        if (hh < NH)
            g_q[(size_t)b * NH * HD + hh * HD + d] = out * SCALE;
        else
            g_kn[(size_t)b * NKV * HD + (hh - NH) * HD + d] = out;
    } else {
        g_vn[(size_t)b * NKV * HD + (hh - NH - NKV) * HD + d] = v;
    }
}

// ------------------------- kernel 4: flash attention, split-KV, absolute-exp -------
__global__ __launch_bounds__(128) void k_attn(const float* __restrict__ pk,
                                              const float* __restrict__ pv,
                                              const int* __restrict__ pidx,
                                              const int* __restrict__ pindptr,
                                              const int* __restrict__ plast) {
    int s = blockIdx.x, kvh = blockIdx.y, b = blockIdx.z;
    int tid = threadIdx.x, w = tid >> 5, lane = tid & 31;
    __shared__ float smq[G * HD];
    __shared__ float so[4][G][HD];
    __shared__ float sl[4][G];

    for (int i = tid; i < G * HD; i += 128)
        smq[i] = g_q[(size_t)b * NH * HD + (kvh * G) * HD + i];
    __syncthreads();
    float4 q[G];
    #pragma unroll
    for (int h = 0; h < G; h++) q[h] = *(float4*)&smq[h * HD + lane * 4];

    int p0 = pindptr[b];
    int npages = pindptr[b + 1] - p0;
    int kvlen = (npages - 1) * PS + plast[b];
    int chunk = (kvlen + SPLIT - 1) / SPLIT;
    int cs = s * chunk, ce = min(cs + chunk, kvlen);
    int kvm1 = kvlen - 1;
    int ce2 = min(ce, kvm1);

    float lv[G];
    float4 o[G];
    #pragma unroll
    for (int h = 0; h < G; h++) {
        lv[h] = 0.f; o[h] = make_float4(0.f, 0.f, 0.f, 0.f);
    }

    for (int pos = cs + w * 2; pos < ce2; pos += 8) {
        int pg0 = pidx[p0 + (pos >> 4)];
        size_t ba = (((size_t)pg0 * PS + (pos & 15)) * NKV + kvh) * HD;
        float4 k4a = *(const float4*)(pk + ba + lane * 4);
        float4 v4a = *(const float4*)(pv + ba + lane * 4);
        int pos1 = pos + 1;
        bool h1 = pos1 < ce2;
        float4 k4b = make_float4(0.f, 0.f, 0.f, 0.f);
        float4 v4b = k4b;
        if (h1) {
            int pg1 = pidx[p0 + (pos1 >> 4)];
            size_t bb = (((size_t)pg1 * PS + (pos1 & 15)) * NKV + kvh) * HD;
            k4b = *(const float4*)(pk + bb + lane * 4);
            v4b = *(const float4*)(pv + bb + lane * 4);
        }
        float sa[G], sb[G];
        #pragma unroll
        for (int h = 0; h < G; h++) {
            sa[h] = q[h].x * k4a.x + q[h].y * k4a.y + q[h].z * k4a.z + q[h].w * k4a.w;
            sb[h] = q[h].x * k4b.x + q[h].y * k4b.y + q[h].z * k4b.z + q[h].w * k4b.w;
        }
        #pragma unroll
        for (int off = 16; off; off >>= 1) {
            #pragma unroll
            for (int h = 0; h < G; h++) {
                sa[h] += __shfl_xor_sync(0xffffffffu, sa[h], off);
                sb[h] += __shfl_xor_sync(0xffffffffu, sb[h], off);
            }
        }
        #pragma unroll
        for (int h = 0; h < G; h++) {
            float p = __expf(sa[h]);
            lv[h] += p;
            o[h].x += p * v4a.x;
            o[h].y += p * v4a.y;
            o[h].z += p * v4a.z;
            o[h].w += p * v4a.w;
        }
        if (h1) {
            #pragma unroll
            for (int h = 0; h < G; h++) {
                float p = __expf(sb[h]);
                lv[h] += p;
                o[h].x += p * v4b.x;
                o[h].y += p * v4b.y;
                o[h].z += p * v4b.z;
                o[h].w += p * v4b.w;
            }
        }
    }

    // appended token (position kvlen-1): warp 0 of the owning split
    if (ce == kvlen && cs < kvlen && w == 0) {
        const float* kp = g_kn + ((size_t)b * NKV + kvh) * HD;
        const float* vp = g_vn + ((size_t)b * NKV + kvh) * HD;
        float4 k4 = *(const float4*)(kp + lane * 4);
        float4 v4 = *(const float4*)(vp + lane * 4);
        float sc[G];
        #pragma unroll
        for (int h = 0; h < G; h++)
            sc[h] = q[h].x * k4.x + q[h].y * k4.y + q[h].z * k4.z + q[h].w * k4.w;
        #pragma unroll
        for (int off = 16; off; off >>= 1)
            #pragma unroll
            for (int h = 0; h < G; h++)
                sc[h] += __shfl_xor_sync(0xffffffffu, sc[h], off);
        #pragma unroll
        for (int h = 0; h < G; h++) {
            float p = __expf(sc[h]);
            lv[h] += p;
            o[h].x += p * v4.x;
            o[h].y += p * v4.y;
            o[h].z += p * v4.z;
            o[h].w += p * v4.w;
        }
    }

    #pragma unroll
    for (int h = 0; h < G; h++) {
        so[w][h][lane * 4 + 0] = o[h].x;
        so[w][h][lane * 4 + 1] = o[h].y;
        so[w][h][lane * 4 + 2] = o[h].z;
        so[w][h][lane * 4 + 3] = o[h].w;
        if (lane == 0) sl[w][h] = lv[h];
    }
    __syncthreads();

    size_t pbase = (size_t)(b * NKV + kvh) * SPLIT + s;
    for (int h = 0; h < G; h++) {
        float Ls = sl[0][h] + sl[1][h] + sl[2][h] + sl[3][h];
        float Od = so[0][h][tid] + so[1][h][tid] + so[2][h][tid] + so[3][h][tid];
        g_pO[(pbase * G + h) * HD + tid] = Od;
        if (tid == 0) g_pL[pbase * G + h] = Ls;
    }
}

// ------------------------- kernel 5: combine attention splits -> g_o [b][k] ----------
__global__ __launch_bounds__(128) void k_attn_comb() {
    int hh = blockIdx.x, b = blockIdx.y, d = threadIdx.x;
    int kvh = hh >> 2, h = hh & 3;
    size_t base0 = (size_t)(b * NKV + kvh) * SPLIT;
    float L = 0.f, Od = 0.f;
    #pragma unroll
    for (int s = 0; s < SPLIT; s++) {
        L  += g_pL[(base0 + s) * G + h];
        Od += g_pO[((base0 + s) * G + h) * HD + d];
    }
    g_o[(size_t)b * NH * HD + hh * HD + d] = Od / L;
}

// ------------------------- kernel 7: h = x + woP; hf = rmsnorm(h) -------------------------
__global__ __launch_bounds__(256) void k_resid1(const float* __restrict__ x,
                                                const float* __restrict__ fw) {
    int b = blockIdx.x, tid = threadIdx.x;
    float hv[16];
    float ss = 0.f;
    #pragma unroll
    for (int i = 0; i < 16; i++) {
        int m = tid + i * 256;
        float t = x[b * DIM + m];
        #pragma unroll
        for (int s = 0; s < SWO; s++)
            t += g_woP[((size_t)s * B + b) * DIM + m];
        hv[i] = t; ss += t * t;
        g_h[(size_t)b * DIM + m] = t;
    }
    ss = blockReduceSum256(ss);
    float r = rsqrtf(ss / (float)DIM + EPS);
    #pragma unroll
    for (int i = 0; i < 16; i++) {
        int m = tid + i * 256;
        g_hf[(size_t)b * DIM + m] = hv[i] * r * fw[m];
    }
}

// ------------------------- kernel 9: silu(w1P) * stem -> g_g [b][k] -------------------------
__global__ __launch_bounds__(256) void k_silu(const float* __restrict__ buffer,
                                              const int* __restrict__ bids) {
    int m = blockIdx.x * 256 + threadIdx.x;
    int b = blockIdx.y;
    float v = 0.f;
    #pragma unroll
    for (int s = 0; s < SW1; s++)
        v += g_w1P[((size_t)s * B + b) * INTER + m];
    float sig = 1.f / (1.f + expf(-v));
    float stem = buffer[(size_t)bids[b] * INTER + m];
    g_g[(size_t)b * INTER + m] = v * sig * stem;
}

// ------------------------- kernel 11: out = h + w2P -------------------------
__global__ __launch_bounds__(256) void k_final(float* __restrict__ out) {
    int idx = blockIdx.x * 256 + threadIdx.x;   // idx = b*DIM + m
    float v = g_h[idx];
    #pragma unroll
    for (int s = 0; s < SW2; s++)
        v += g_w2P[(size_t)s * B * DIM + idx];
    out[idx] = v;
}

// ------------------------- launch -------------------------
extern "C" void kernel_launch(void* const* d_in, const int* in_sizes, int n_in,
                              void* d_out, int out_size) {
    (void)in_sizes; (void)n_in; (void)out_size;
    const float* x        = (const float*)d_in[0];
    const float* buffer   = (const float*)d_in[1];
    const float* paged_k  = (const float*)d_in[2];
    const float* paged_v  = (const float*)d_in[3];
    const float* wqkv     = (const float*)d_in[4];
    const float* wo       = (const float*)d_in[5];
    const float* w1       = (const float*)d_in[6];
    const float* w2       = (const float*)d_in[7];
    const float* attn_w   = (const float*)d_in[8];
    const float* ffn_w    = (const float*)d_in[9];
    const int*   bids     = (const int*)d_in[10];
    const int*   offsets  = (const int*)d_in[11];
    const int*   pidx     = (const int*)d_in[13];
    const int*   pindptr  = (const int*)d_in[14];
    const int*   plast    = (const int*)d_in[15];
    float* out = (float*)d_out;

    float* xa;   cudaGetSymbolAddress((void**)&xa,   g_xa);
    float* qkvP; cudaGetSymbolAddress((void**)&qkvP, g_qkvP);
    float* oA;   cudaGetSymbolAddress((void**)&oA,   g_o);
    float* woP;  cudaGetSymbolAddress((void**)&woP,  g_woP);
    float* hf;   cudaGetSymbolAddress((void**)&hf,   g_hf);
    float* w1P;  cudaGetSymbolAddress((void**)&w1P,  g_w1P);
    float* gg;   cudaGetSymbolAddress((void**)&gg,   g_g);
    float* w2P;  cudaGetSymbolAddress((void**)&w2P,  g_w2P);

    k_rms_x<<<B, 256>>>(x, attn_w);
    k_gemm_mma<<<dim3(QKV_M / 128, SQKV), 256>>>(wqkv, xa, qkvP, QKV_M, DIM, DIM / SQKV);
    k_rope<<<dim3(B, 48), 128>>>(offsets);
    k_attn<<<dim3(SPLIT, NKV, B), 128>>>(paged_k, paged_v, pidx, pindptr, plast);
    k_attn_comb<<<dim3(NH, B), 128>>>();
    k_gemm_mma<<<dim3(DIM / 128, SWO), 256>>>(wo, oA, woP, DIM, NH * HD, (NH * HD) / SWO);
    k_resid1<<<B, 256>>>(x, ffn_w);
    k_gemm_mma<<<dim3(INTER / 128, SW1), 256>>>(w1, hf, w1P, INTER, DIM, DIM / SW1);
    k_silu<<<dim3(INTER / 256, B), 256>>>(buffer, bids);
    k_gemm_mma<<<dim3(DIM / 128, SW2), 256>>>(w2, gg, w2P, DIM, INTER, INTER / SW2);
    k_final<<<(B * DIM) / 256, 256>>>(out);
}